// round 15
// baseline (speedup 1.0000x reference)
#include <cuda_runtime.h>
#include <cuda_fp16.h>
#include <math.h>
#include <stdint.h>

// Problem constants
#define F 18
#define PP 128
#define HH 256
#define NCLS 625
#define NTOK (F*PP)            // 2304
#define NELEM (F*PP*HH)        // 589824
#define TPAIRS 1152            // NTOK/2
#define KG 768                 // gproj K dimension (3 scales x 256)
// frame-pair slot bases/strides: s2 (3 slots), s4 (7), s6 (11)
#define SBASE0 0
#define SBASE1 54
#define SBASE2 180
#define NSLOTS 378

// -------- device scratch (allocation-free) --------
__device__ __half d_Xh[NELEM];             // fp16 inputs (for QKV mma)
__device__ __half d_Qh[3*NELEM];
__device__ __half d_Kh[3*NELEM];
__device__ uint32_t d_Vt[3*8*32*TPAIRS];   // [si][h][dim][tokpair] packed half2
__device__ __half d_Nbuf[(size_t)NSLOTS*128*256];  // unnormalized PV per frame-pair
__device__ float d_Dbuf[(size_t)NSLOTS*128*8];     // exp-sums per frame-pair [slot][q][h]
__device__ __half d_G[NTOK*KG];            // combined attn [token][si*256+k] fp16
__device__ __half d_Wqkvh[9*HH*HH];        // QKV weights transposed [si*3+which][n][k] fp16
__device__ __half d_Wgt[HH*KG];            // gproj weights [n][si*256+k] fp16
__device__ float d_bsum[HH];               // 0.25*(bo0+bo1+bo2)
__device__ float d_vsum[2*F*HH];           // per-iter per-frame column sums of gproj acc
__device__ float d_sig[NTOK];              // iter-0 sigmoid values
__device__ float d_sigacc[NTOK];           // iter-1 raw halt dots (pre-sigmoid)

__device__ __forceinline__ uint32_t packh2(float a, float b) {
    __half2 h = __floats2half2_rn(a, b);
    return *(uint32_t*)&h;
}

__device__ __forceinline__ uint32_t h2ex2(uint32_t x) {
    uint32_t y;
    asm("ex2.approx.f16x2 %0, %1;" : "=r"(y) : "r"(x));
    return y;
}

__device__ __forceinline__ void cp16(uint32_t saddr, const void* g) {
    asm volatile("cp.async.cg.shared.global [%0], [%1], 16;\n" :: "r"(saddr), "l"(g));
}
#define CP_COMMIT() asm volatile("cp.async.commit_group;\n" ::: "memory")
#define CP_WAIT3()  asm volatile("cp.async.wait_group 3;\n" ::: "memory")
#define CP_WAIT2()  asm volatile("cp.async.wait_group 2;\n" ::: "memory")
#define CP_WAIT1()  asm volatile("cp.async.wait_group 1;\n" ::: "memory")
#define CP_WAIT0()  asm volatile("cp.async.wait_group 0;\n" ::: "memory")

// mma.sync m16n8k16 fp16 -> fp32 accumulate in-place
__device__ __forceinline__ void mma_f16(float c[4], const uint32_t a[4],
                                        uint32_t b0, uint32_t b1)
{
    asm volatile(
        "mma.sync.aligned.m16n8k16.row.col.f32.f16.f16.f32 "
        "{%0,%1,%2,%3}, {%4,%5,%6,%7}, {%8,%9}, {%0,%1,%2,%3};\n"
        : "+f"(c[0]), "+f"(c[1]), "+f"(c[2]), "+f"(c[3])
        : "r"(a[0]), "r"(a[1]), "r"(a[2]), "r"(a[3]), "r"(b0), "r"(b1));
}

// =================== iter-0 halting + X->fp16 (fused) ===================
__global__ void __launch_bounds__(256)
halt_sig_k(const float* __restrict__ x, const float* __restrict__ hW,
           const float* __restrict__ hb, float* __restrict__ sig,
           __half* __restrict__ Xh)
{
    int warp = threadIdx.x >> 5;
    int lane = threadIdx.x & 31;
    int pos = blockIdx.x * 8 + warp;
    const float* xp0 = x + (size_t)pos * HH + lane * 8;
    const float* xp1 = x + (size_t)(pos + TPAIRS) * HH + lane * 8;
    const float* wp = hW + lane * 8;
    float4 a0 = *(const float4*)xp0;
    float4 a1 = *(const float4*)(xp0 + 4);
    float4 b0 = *(const float4*)xp1;
    float4 b1 = *(const float4*)(xp1 + 4);
    float4 w0 = *(const float4*)wp;
    float4 w1 = *(const float4*)(wp + 4);
    uint4 ha, hb4;
    ha.x = packh2(a0.x, a0.y);  ha.y = packh2(a0.z, a0.w);
    ha.z = packh2(a1.x, a1.y);  ha.w = packh2(a1.z, a1.w);
    hb4.x = packh2(b0.x, b0.y); hb4.y = packh2(b0.z, b0.w);
    hb4.z = packh2(b1.x, b1.y); hb4.w = packh2(b1.z, b1.w);
    *(uint4*)&Xh[(size_t)pos * HH + lane * 8] = ha;
    *(uint4*)&Xh[(size_t)(pos + TPAIRS) * HH + lane * 8] = hb4;

    float acc0 = a0.x * w0.x + a0.y * w0.y + a0.z * w0.z + a0.w * w0.w
               + a1.x * w1.x + a1.y * w1.y + a1.z * w1.z + a1.w * w1.w;
    float acc1 = b0.x * w0.x + b0.y * w0.y + b0.z * w0.z + b0.w * w0.w
               + b1.x * w1.x + b1.y * w1.y + b1.z * w1.z + b1.w * w1.w;
    #pragma unroll
    for (int off = 16; off > 0; off >>= 1) {
        acc0 += __shfl_xor_sync(0xffffffffu, acc0, off);
        acc1 += __shfl_xor_sync(0xffffffffu, acc1, off);
    }
    if (lane == 0) {
        sig[pos] = 1.f / (1.f + __expf(-(acc0 + hb[0])));
        sig[pos + TPAIRS] = 1.f / (1.f + __expf(-(acc1 + hb[0])));
    }
}

// =================== merged setup: weight conversions + misc init ===================
// z in [0,9): QKV weights. z in [9,12): gproj weights. z==12: bsum + zero buffers.
__global__ void __launch_bounds__(256)
setup_k(const float* __restrict__ Wq, const float* __restrict__ Wk,
        const float* __restrict__ Wv, const float* __restrict__ Wo,
        const float* __restrict__ bo,
        __half* __restrict__ Wqkvh, __half* __restrict__ Wgt,
        float* __restrict__ bsum, float* __restrict__ vsum,
        float* __restrict__ sigacc)
{
    __shared__ float t[32][33];
    int z = blockIdx.z;
    int tx = threadIdx.x, ty = threadIdx.y;     // 32 x 8
    if (z == 12) {
        if (blockIdx.x != 0 || blockIdx.y != 0) return;
        int tid = ty * 32 + tx;
        if (tid < HH) bsum[tid] = 0.25f * (bo[tid] + bo[HH + tid] + bo[2 * HH + tid]);
        for (int i = tid; i < 2 * F * HH; i += 256) vsum[i] = 0.f;
        for (int i = tid; i < NTOK; i += 256) sigacc[i] = 0.f;
        return;
    }
    int k0 = blockIdx.x * 32, n0 = blockIdx.y * 32;
    if (z < 9) {
        int si = z / 3, which = z - si * 3;
        const float* W = (which == 0) ? Wq : ((which == 1) ? Wk : Wv);
        const float* src = W + (size_t)si * HH * HH;
        __half* dst = Wqkvh + (size_t)z * HH * HH;
        #pragma unroll
        for (int r = ty; r < 32; r += 8)
            t[r][tx] = src[(size_t)(k0 + r) * HH + n0 + tx];
        __syncthreads();
        #pragma unroll
        for (int r = ty; r < 32; r += 8)
            dst[(size_t)(n0 + r) * HH + k0 + tx] = __float2half(t[tx][r]);
    } else {
        int si = z - 9;
        const float* src = Wo + (size_t)si * HH * HH;
        #pragma unroll
        for (int r = ty; r < 32; r += 8)
            t[r][tx] = src[(size_t)(k0 + r) * HH + n0 + tx];
        __syncthreads();
        #pragma unroll
        for (int r = ty; r < 32; r += 8)
            Wgt[(size_t)(n0 + r) * KG + si * HH + k0 + tx] = __float2half(t[tx][r]);
    }
}

// =================== fp16 mma GEMM mainloop, tile 128x128, NS-stage pipeline ===================
#define OSTRIDE 36
#define GBUF (128 * OSTRIDE)
template <int NS>
__device__ __forceinline__ void mma_mainloop(const __half* __restrict__ A, int bm, int lda,
                                             const __half* __restrict__ Bw, int bn, int ldb,
                                             int kdim, uint32_t* sbuf, float acc[2][8][4])
{
    const int tid  = threadIdx.x;
    const int warp = tid >> 5;
    const int lane = tid & 31;
    const int gid  = lane >> 2;
    const int tig  = lane & 3;
    const int wm = (warp & 3) * 32;
    const int wn = (warp >> 2) * 64;
    const uint32_t sb = (uint32_t)__cvta_generic_to_shared(sbuf);

    #pragma unroll
    for (int mt = 0; mt < 2; mt++)
        #pragma unroll
        for (int nt = 0; nt < 8; nt++)
            #pragma unroll
            for (int i = 0; i < 4; i++) acc[mt][nt][i] = 0.f;

    auto issue = [&](int kc, int st) {
        uint32_t aoff = sb + (uint32_t)(2 * st) * (GBUF * 4);
        uint32_t boff = aoff + GBUF * 4;
        for (int i = tid; i < 1024; i += 256) {
            int m = i >> 3, q = i & 7;
            uint32_t so = (uint32_t)(m * OSTRIDE + q * 4) * 4;
            cp16(aoff + so, &A[(size_t)(bm + m) * lda + kc + q * 8]);
            cp16(boff + so, &Bw[(size_t)(bn + m) * ldb + kc + q * 8]);
        }
        CP_COMMIT();
    };

    const int nchunks = kdim >> 6;
    #pragma unroll
    for (int p = 0; p < NS - 1; p++)
        if (p < nchunks) issue(p * 64, p);

    for (int kci = 0; kci < nchunks; kci++) {
        int nxt = kci + NS - 1;
        if (nxt < nchunks) issue(nxt * 64, nxt % NS);
        int rem = ((nxt < nchunks - 1) ? nxt : (nchunks - 1)) - kci;
        if (rem >= 3) { CP_WAIT3(); }
        else if (rem == 2) { CP_WAIT2(); }
        else if (rem == 1) { CP_WAIT1(); }
        else { CP_WAIT0(); }
        __syncthreads();
        uint32_t* As = sbuf + 2 * (kci % NS) * GBUF;
        uint32_t* Bs = As + GBUF;
        #pragma unroll
        for (int ks = 0; ks < 4; ks++) {
            uint32_t a[2][4];
            #pragma unroll
            for (int mt = 0; mt < 2; mt++) {
                int r0 = (wm + mt * 16 + gid) * OSTRIDE + ks * 8;
                int r1 = (wm + mt * 16 + gid + 8) * OSTRIDE + ks * 8;
                a[mt][0] = As[r0 + tig];
                a[mt][1] = As[r1 + tig];
                a[mt][2] = As[r0 + tig + 4];
                a[mt][3] = As[r1 + tig + 4];
            }
            #pragma unroll
            for (int nt = 0; nt < 8; nt++) {
                int nr = (wn + nt * 8 + gid) * OSTRIDE + ks * 8;
                uint32_t b0 = Bs[nr + tig];
                uint32_t b1 = Bs[nr + tig + 4];
                #pragma unroll
                for (int mt = 0; mt < 2; mt++)
                    mma_f16(acc[mt][nt], a[mt], b0, b1);
            }
        }
        __syncthreads();
    }
}

// QKV mma GEMM: grid (18, 2, 9); z: si=z/3, which=z%3.
__global__ void __launch_bounds__(256)
gemm_qkv_mma_k(const __half* __restrict__ Xh, const __half* __restrict__ Wt,
               const float* __restrict__ bq, const float* __restrict__ bk,
               const float* __restrict__ bv,
               __half* __restrict__ Q, __half* __restrict__ K,
               uint32_t* __restrict__ Vt)
{
    __shared__ uint32_t sbuf[4 * GBUF];
    int z = blockIdx.z;
    int si = z / 3, which = z - si * 3;
    int bm = blockIdx.x * 128, bn = blockIdx.y * 128;

    float acc[2][8][4];
    mma_mainloop<2>(Xh, bm, HH, Wt + (size_t)z * HH * HH, bn, HH, HH, sbuf, acc);

    const int tid  = threadIdx.x;
    const int warp = tid >> 5;
    const int lane = tid & 31;
    const int gid  = lane >> 2;
    const int tig  = lane & 3;
    const int wm = (warp & 3) * 32;
    const int wn = (warp >> 2) * 64;

    if (which < 2) {
        const float* bias = ((which == 0) ? bq : bk) + si * HH;
        __half* C = ((which == 0) ? Q : K) + (size_t)si * NELEM;
        float oscale = (which == 0) ? (0.17677669529663687f * 1.4426950408889634f) : 1.0f;
        #pragma unroll
        for (int nt = 0; nt < 8; nt++) {
            int n = bn + wn + nt * 8 + 2 * tig;
            float b0 = bias[n], b1 = bias[n + 1];
            #pragma unroll
            for (int mt = 0; mt < 2; mt++) {
                int m = bm + wm + mt * 16 + gid;
                *(uint32_t*)&C[(size_t)m * 256 + n] =
                    packh2((acc[mt][nt][0] + b0) * oscale, (acc[mt][nt][1] + b1) * oscale);
                *(uint32_t*)&C[(size_t)(m + 8) * 256 + n] =
                    packh2((acc[mt][nt][2] + b0) * oscale, (acc[mt][nt][3] + b1) * oscale);
            }
        }
    } else {
        const float* bias = bv + si * HH;
        __half* stag = (__half*)sbuf;            // [128 tok][stride 130]
        __syncthreads();
        #pragma unroll
        for (int nt = 0; nt < 8; nt++) {
            int nl = wn + nt * 8 + 2 * tig;
            float b0 = bias[bn + nl], b1 = bias[bn + nl + 1];
            #pragma unroll
            for (int mt = 0; mt < 2; mt++) {
                int ml = wm + mt * 16 + gid;
                *(uint32_t*)&stag[ml * 130 + nl] =
                    packh2(acc[mt][nt][0] + b0, acc[mt][nt][1] + b1);
                *(uint32_t*)&stag[(ml + 8) * 130 + nl] =
                    packh2(acc[mt][nt][2] + b0, acc[mt][nt][3] + b1);
            }
        }
        __syncthreads();
        const int tpg0 = bm >> 1;
        uint32_t* vtb = Vt + (size_t)si * 8 * 32 * TPAIRS;
        #pragma unroll
        for (int j = tid; j < 8192; j += 256) {
            int tp = j & 63;
            int nl = j >> 6;
            int ncol = bn + nl;
            int h = ncol >> 5, d = ncol & 31;
            __half lo = stag[(2 * tp) * 130 + nl];
            __half hi = stag[(2 * tp + 1) * 130 + nl];
            __half2 pr = __halves2half2(lo, hi);
            vtb[((size_t)(h * 32 + d)) * TPAIRS + tpg0 + tp] = *(uint32_t*)&pr;
        }
    }
}

// =================== frame-pair attention: N/D decomposition ===================
#define KPSTRIDE 36
#define VTSTRIDE 36
__global__ void __launch_bounds__(256, 3)
attn_nd_k(const __half* __restrict__ Qg, const __half* __restrict__ Kg,
          const uint32_t* __restrict__ Vt, __half* __restrict__ Nbuf,
          float* __restrict__ Dbuf)
{
    __shared__ uint32_t Kp[2][64 * KPSTRIDE];
    __shared__ uint32_t Vs[2][32 * VTSTRIDE];

    int pid = blockIdx.x;
    int si, fq, d, slot, s;
    if (pid < 198)      { si = 2; s = 6; fq = pid / 11; d = pid - fq * 11; slot = SBASE2 + fq * 11 + d; }
    else if (pid < 324) { pid -= 198; si = 1; s = 4; fq = pid / 7; d = pid - fq * 7; slot = SBASE1 + fq * 7 + d; }
    else                { pid -= 324; si = 0; s = 2; fq = pid / 3; d = pid - fq * 3; slot = SBASE0 + fq * 3 + d; }
    const int fk = fq + d - (s - 1);
    if (fk < 0 || fk > 17) return;

    const int tid  = threadIdx.x;
    const int warp = tid >> 5;
    const int lane = tid & 31;
    const int gid  = lane >> 2;
    const int tig  = lane & 3;
    const int h    = blockIdx.y;

    const __half* Q = Qg + (size_t)si * NELEM;
    const __half* K = Kg + (size_t)si * NELEM;
    const uint32_t* Vtb = Vt + ((size_t)si * 8 + h) * 32 * TPAIRS;

    const uint32_t kpb = (uint32_t)__cvta_generic_to_shared(&Kp[0][0]);
    const uint32_t vsb = (uint32_t)__cvta_generic_to_shared(&Vs[0][0]);

    auto issueKV = [&](int kb, int st) {
        {
            const __half* kg = K + ((size_t)(fk * PP + kb)) * HH + h * 32;
            int key = tid >> 2, q = tid & 3;
            cp16(kpb + (uint32_t)(st * 64 * KPSTRIDE + key * KPSTRIDE + q * 4) * 4,
                 kg + (size_t)key * HH + q * 8);
        }
        {
            const uint32_t* vg = Vtb + ((fk * PP + kb) >> 1);
            int dd = tid >> 3, q = tid & 7;
            cp16(vsb + (uint32_t)(st * 32 * VTSTRIDE + dd * VTSTRIDE + q * 4) * 4,
                 vg + (size_t)dd * TPAIRS + q * 4);
        }
        CP_COMMIT();
    };

    const int qloc = warp * 16 + gid;
    const int qrow = fq * PP + qloc;
    uint32_t qa[2][4];
    #pragma unroll
    for (int ks = 0; ks < 2; ks++) {
        const uint32_t* q0 = (const uint32_t*)(Q + (size_t)qrow * HH + h * 32 + ks * 16);
        const uint32_t* q1 = (const uint32_t*)(Q + (size_t)(qrow + 8) * HH + h * 32 + ks * 16);
        qa[ks][0] = q0[tig];
        qa[ks][1] = q1[tig];
        qa[ks][2] = q0[tig + 4];
        qa[ks][3] = q1[tig + 4];
    }

    float o[4][4];
    #pragma unroll
    for (int v = 0; v < 4; v++)
        #pragma unroll
        for (int i = 0; i < 4; i++) o[v][i] = 0.f;
    float l0 = 0.f, l1 = 0.f;

    issueKV(0, 0);
    #pragma unroll
    for (int kt = 0; kt < 2; kt++) {
        if (kt == 0) { issueKV(64, 1); CP_WAIT1(); } else { CP_WAIT0(); }
        __syncthreads();

        float sc[8][4];
        #pragma unroll
        for (int t = 0; t < 8; t++) {
            sc[t][0] = sc[t][1] = sc[t][2] = sc[t][3] = 0.f;
            const int krow = (8 * t + gid) * KPSTRIDE;
            #pragma unroll
            for (int ks = 0; ks < 2; ks++) {
                uint32_t b0 = Kp[kt][krow + ks * 8 + tig];
                uint32_t b1 = Kp[kt][krow + ks * 8 + tig + 4];
                mma_f16(sc[t], qa[ks], b0, b1);
            }
        }

        uint32_t e0[8], e1[8];
        #pragma unroll
        for (int t = 0; t < 8; t++) {
            e0[t] = h2ex2(packh2(sc[t][0], sc[t][1]));
            e1[t] = h2ex2(packh2(sc[t][2], sc[t][3]));
            float2 f0 = __half22float2(*(__half2*)&e0[t]);
            float2 f1 = __half22float2(*(__half2*)&e1[t]);
            l0 += f0.x + f0.y;
            l1 += f1.x + f1.y;
        }

        #pragma unroll
        for (int u = 0; u < 4; u++) {
            uint32_t pa[4];
            pa[0] = e0[2*u];
            pa[1] = e1[2*u];
            pa[2] = e0[2*u+1];
            pa[3] = e1[2*u+1];
            #pragma unroll
            for (int v = 0; v < 4; v++) {
                uint32_t b0 = Vs[kt][(gid + 8 * v) * VTSTRIDE + 8 * u + tig];
                uint32_t b1 = Vs[kt][(gid + 8 * v) * VTSTRIDE + 8 * u + tig + 4];
                mma_f16(o[v], pa, b0, b1);
            }
        }
        __syncthreads();
    }

    l0 += __shfl_xor_sync(0xffffffffu, l0, 1);
    l0 += __shfl_xor_sync(0xffffffffu, l0, 2);
    l1 += __shfl_xor_sync(0xffffffffu, l1, 1);
    l1 += __shfl_xor_sync(0xffffffffu, l1, 2);

    __half* Nb = Nbuf + ((size_t)slot * 128) * 256 + h * 32;
    #pragma unroll
    for (int v = 0; v < 4; v++) {
        *(uint32_t*)&Nb[(size_t)qloc * 256 + v * 8 + 2 * tig] = packh2(o[v][0], o[v][1]);
        *(uint32_t*)&Nb[(size_t)(qloc + 8) * 256 + v * 8 + 2 * tig] = packh2(o[v][2], o[v][3]);
    }
    if (tig == 0) {
        Dbuf[((size_t)slot * 128 + qloc) * 8 + h] = l0;
        Dbuf[((size_t)slot * 128 + qloc + 8) * 8 + h] = l1;
    }
}

// =================== combine: sliding-window N/D -> G ===================
__global__ void __launch_bounds__(256)
combine_k(const __half* __restrict__ Nbuf, const float* __restrict__ Dbuf,
          __half* __restrict__ G)
{
    const int t = blockIdx.x;
    const int c = threadIdx.x;
    const int f = t >> 7, pos = t & 127;
    const int hh = c >> 5;

    const int ss[3]    = {2, 4, 6};
    const int strd[3]  = {3, 7, 11};
    const int sbase[3] = {SBASE0, SBASE1, SBASE2};

    #pragma unroll
    for (int si = 0; si < 3; si++) {
        const int s = ss[si];
        const int slotbase = sbase[si] + f * strd[si];
        const int nw = F - s + 1;
        const int wlo = max(0, f - s + 1);
        const int whi = min(f, nw - 1);
        const int count = whi - wlo + 1;

        float num = 0.f, den = 0.f;
        const int d0 = wlo - f + s - 1;
        for (int dd = 0; dd < s; dd++) {
            int sl = slotbase + d0 + dd;
            num += __half2float(Nbuf[((size_t)sl * 128 + pos) * 256 + c]);
            den += Dbuf[((size_t)sl * 128 + pos) * 8 + hh];
        }
        float total = num / den;
        for (int w = wlo + 1; w <= whi; w++) {
            int slout = slotbase + (w - 1) - f + s - 1;
            int slin  = slotbase + w - f + 2 * s - 2;
            num += __half2float(Nbuf[((size_t)slin * 128 + pos) * 256 + c])
                 - __half2float(Nbuf[((size_t)slout * 128 + pos) * 256 + c]);
            den += Dbuf[((size_t)slin * 128 + pos) * 8 + hh]
                 - Dbuf[((size_t)slout * 128 + pos) * 8 + hh];
            total += num / den;
        }
        G[(size_t)t * KG + si * HH + c] = __float2half(total * (0.25f / (float)count));
    }
}

// =================== gproj GEMM + colsum + X + fused next-iter halt dot ===================
// grid (18, 2). 4-stage pipeline (12 k-chunks). When writeX: also writes fp16 Xh
// and accumulates raw halt dots v·hW into sigacc (sigmoid applied in classify).
__global__ void __launch_bounds__(256)
gemm_gproj_mma_k(const __half* __restrict__ G, const __half* __restrict__ Wgt,
                 const float* __restrict__ bsum, float* __restrict__ vsum,
                 __half* __restrict__ Xh, const float* __restrict__ hW,
                 float* __restrict__ sigacc, int writeX)
{
    __shared__ uint32_t sbuf[8 * GBUF];
    int bm = blockIdx.x * 128, bn = blockIdx.y * 128;

    float acc[2][8][4];
    mma_mainloop<4>(G, bm, KG, Wgt, bn, KG, KG, sbuf, acc);

    const int tid  = threadIdx.x;
    const int warp = tid >> 5;
    const int lane = tid & 31;
    const int gid  = lane >> 2;
    const int tig  = lane & 3;
    const int wm = (warp & 3) * 32;
    const int wn = (warp >> 2) * 64;
    const int f = bm >> 7;
    float* vs = vsum + f * HH;

    float hd[4] = {0.f, 0.f, 0.f, 0.f};   // halt partial dots: rows m, m+8 (mt=0,1)

    #pragma unroll
    for (int nt = 0; nt < 8; nt++) {
        int n = bn + wn + nt * 8 + 2 * tig;
        float b0 = bsum[n], b1 = bsum[n + 1];
        float s0 = acc[0][nt][0] + acc[0][nt][2] + acc[1][nt][0] + acc[1][nt][2];
        float s1 = acc[0][nt][1] + acc[0][nt][3] + acc[1][nt][1] + acc[1][nt][3];
        #pragma unroll
        for (int off = 4; off < 32; off <<= 1) {
            s0 += __shfl_xor_sync(0xffffffffu, s0, off);
            s1 += __shfl_xor_sync(0xffffffffu, s1, off);
        }
        if (gid == 0) {
            atomicAdd(&vs[n], s0);
            atomicAdd(&vs[n + 1], s1);
        }
        if (writeX) {
            float hw0 = hW[n], hw1 = hW[n + 1];
            #pragma unroll
            for (int mt = 0; mt < 2; mt++) {
                int m = bm + wm + mt * 16 + gid;
                float v0 = acc[mt][nt][0] + b0, v1 = acc[mt][nt][1] + b1;
                float v2 = acc[mt][nt][2] + b0, v3 = acc[mt][nt][3] + b1;
                *(uint32_t*)&Xh[(size_t)m * 256 + n] = packh2(v0, v1);
                *(uint32_t*)&Xh[(size_t)(m + 8) * 256 + n] = packh2(v2, v3);
                hd[mt * 2]     += v0 * hw0 + v1 * hw1;
                hd[mt * 2 + 1] += v2 * hw0 + v3 * hw1;
            }
        }
    }

    if (writeX) {
        #pragma unroll
        for (int i = 0; i < 4; i++) {
            hd[i] += __shfl_xor_sync(0xffffffffu, hd[i], 1);
            hd[i] += __shfl_xor_sync(0xffffffffu, hd[i], 2);
        }
        if (tig == 0) {
            #pragma unroll
            for (int mt = 0; mt < 2; mt++) {
                int m = bm + wm + mt * 16 + gid;
                atomicAdd(&sigacc[m], hd[mt * 2]);
                atomicAdd(&sigacc[m + 8], hd[mt * 2 + 1]);
            }
        }
    }
}

// =================== classifier: ACT + weighted colsum combine + GEMV ===================
__global__ void classify_k(const float* __restrict__ vsum, const float* __restrict__ sig0,
                           const float* __restrict__ sigacc, const float* __restrict__ hb,
                           const float* __restrict__ bsum,
                           const float* __restrict__ clsW, const float* __restrict__ clsb,
                           float* __restrict__ out)
{
    __shared__ float cs[HH];
    __shared__ float pf0s[F], pf1s[F], w0s[F], w1s[F];
    int tid = threadIdx.x;        // 128
    int warp = tid >> 5, lane = tid & 31;

    // per-frame halting means: warp0 -> iter0 (sigmoids stored), warp1 -> iter1 (raw dots)
    if (warp == 0) {
        for (int f = 0; f < F; f++) {
            float4 v = *(const float4*)&sig0[f * PP + lane * 4];
            float a = v.x + v.y + v.z + v.w;
            #pragma unroll
            for (int off = 16; off > 0; off >>= 1)
                a += __shfl_xor_sync(0xffffffffu, a, off);
            if (lane == 0) pf0s[f] = a * (1.f / 128.f);
        }
    } else if (warp == 1) {
        float hbv = hb[0];
        for (int f = 0; f < F; f++) {
            float4 v = *(const float4*)&sigacc[f * PP + lane * 4];
            float a = 1.f / (1.f + __expf(-(v.x + hbv)))
                    + 1.f / (1.f + __expf(-(v.y + hbv)))
                    + 1.f / (1.f + __expf(-(v.z + hbv)))
                    + 1.f / (1.f + __expf(-(v.w + hbv)));
            #pragma unroll
            for (int off = 16; off > 0; off >>= 1)
                a += __shfl_xor_sync(0xffffffffu, a, off);
            if (lane == 0) pf1s[f] = a * (1.f / 128.f);
        }
    }
    __syncthreads();
    if (tid == 0) {
        for (int f = 0; f < F; f++) {
            float pf0 = pf0s[f], pf1 = pf1s[f];
            // iter 0 (pt=rt=0, run=1)
            float nh   = (pf0 > 0.99f) ? 1.f : 0.f;
            float run2 = (pf0 <= 0.99f) ? 1.f : 0.f;
            float pt = pf0 * run2;
            float rt = nh * (1.f - pt);
            pt = pt + nh * rt;
            w0s[f] = pf0 * run2 + nh * rt;
            // iter 1
            float run = (pt < 1.0f) ? 1.f : 0.f;
            float t = pt + pf1 * run;
            nh   = (t > 0.99f)  ? run : 0.f;
            run2 = (t <= 0.99f) ? run : 0.f;
            pt = pt + pf1 * run2;
            rt = rt + nh * (1.f - pt);
            pt = pt + nh * rt;
            w1s[f] = pf1 * run2 + nh * rt;
        }
    }
    __syncthreads();

    for (int h = tid; h < HH; h += 128) {
        float s = 0.f;
        float bb = 128.f * bsum[h];
        #pragma unroll
        for (int f = 0; f < F; f++) {
            float w0 = w0s[f], w1 = w1s[f];
            float v0 = vsum[f * HH + h] + bb;
            float v1 = vsum[F * HH + f * HH + h] + bb;
            s += w1 * v1 + (1.f - w1) * w0 * v0;
        }
        cs[h] = s;
    }
    __syncthreads();
    int j = blockIdx.x * 128 + tid;
    if (j < NCLS) {
        float acc = clsb[j];
        for (int h = 0; h < HH; h++) acc = fmaf(cs[h], clsW[h * NCLS + j], acc);
        out[j] = acc;
    }
}

// =================== host launch ===================
extern "C" void kernel_launch(void* const* d_in, const int* in_sizes, int n_in,
                              void* d_out, int out_size)
{
    (void)in_sizes; (void)n_in; (void)out_size;
    const float* embed  = (const float*)d_in[0];
    const float* halt_W = (const float*)d_in[3];
    const float* halt_b = (const float*)d_in[4];
    const float* cls_W  = (const float*)d_in[8];
    const float* cls_b  = (const float*)d_in[9];
    const float* Wq = (const float*)d_in[10];
    const float* bq = (const float*)d_in[11];
    const float* Wk = (const float*)d_in[12];
    const float* bk = (const float*)d_in[13];
    const float* Wv = (const float*)d_in[14];
    const float* bv = (const float*)d_in[15];
    const float* Wo = (const float*)d_in[16];
    const float* bo = (const float*)d_in[17];
    float* out = (float*)d_out;

    float *sig, *sigacc, *bsum, *vsum, *Dbuf;
    __half *Xh, *Qh, *Kh, *Nbuf, *G, *Wqkvh, *Wgt;
    uint32_t *Vt;
    cudaGetSymbolAddress((void**)&Xh,      d_Xh);
    cudaGetSymbolAddress((void**)&Qh,      d_Qh);
    cudaGetSymbolAddress((void**)&Kh,      d_Kh);
    cudaGetSymbolAddress((void**)&Vt,      d_Vt);
    cudaGetSymbolAddress((void**)&Nbuf,    d_Nbuf);
    cudaGetSymbolAddress((void**)&Dbuf,    d_Dbuf);
    cudaGetSymbolAddress((void**)&G,       d_G);
    cudaGetSymbolAddress((void**)&Wqkvh,   d_Wqkvh);
    cudaGetSymbolAddress((void**)&Wgt,     d_Wgt);
    cudaGetSymbolAddress((void**)&bsum,    d_bsum);
    cudaGetSymbolAddress((void**)&vsum,    d_vsum);
    cudaGetSymbolAddress((void**)&sig,     d_sig);
    cudaGetSymbolAddress((void**)&sigacc,  d_sigacc);

    // merged setup: weights + bias-sum + zeroing
    {
        dim3 b(32, 8);
        dim3 g(8, 8, 13);
        setup_k<<<g, b>>>(Wq, Wk, Wv, Wo, bo, Wqkvh, Wgt, bsum, vsum, sigacc);
    }
    // iter-0 halting + fp16 X conversion (fused)
    halt_sig_k<<<TPAIRS / 8, 256>>>(embed, halt_W, halt_b, sig, Xh);

    for (int iter = 0; iter < 2; iter++) {
        // QKV (fp16 tensor GEMM) for all 3 scales; V written transposed (Vt)
        dim3 gq(NTOK / 128, 2, 9);
        gemm_qkv_mma_k<<<gq, 256>>>(Xh, Wqkvh, bq, bk, bv, Qh, Kh, Vt);

        // frame-pair attention (N/D decomposition): 378 slots x 8 heads
        dim3 ga(NSLOTS, 8);
        attn_nd_k<<<ga, 256>>>(Qh, Kh, Vt, Nbuf, Dbuf);

        // sliding-window combine -> G
        combine_k<<<NTOK, 256>>>(Nbuf, Dbuf, G);

        // fused projection GEMM + colsum (+Xh + next-iter halt dot on iter 0)
        dim3 gg(NTOK / 128, 2);
        gemm_gproj_mma_k<<<gg, 256>>>(G, Wgt, bsum, vsum + iter * F * HH, Xh,
                                      halt_W, sigacc, iter == 0 ? 1 : 0);
    }
    classify_k<<<(NCLS + 127) / 128, 128>>>(vsum, sig, sigacc, halt_b, bsum,
                                            cls_W, cls_b, out);
}

// round 16
// speedup vs baseline: 1.0273x; 1.0273x over previous
#include <cuda_runtime.h>
#include <cuda_fp16.h>
#include <math.h>
#include <stdint.h>

// Problem constants
#define F 18
#define PP 128
#define HH 256
#define NCLS 625
#define NTOK (F*PP)            // 2304
#define NELEM (F*PP*HH)        // 589824
#define TPAIRS 1152            // NTOK/2
#define KG 768                 // gproj K dimension (3 scales x 256)
// frame-pair slot bases/strides: s2 (3 slots), s4 (7), s6 (11)
#define SBASE0 0
#define SBASE1 54
#define SBASE2 180
#define NSLOTS 378

// -------- device scratch (allocation-free) --------
__device__ __half d_Xh[NELEM];             // fp16 inputs (for QKV mma)
__device__ __half d_Qh[3*NELEM];
__device__ __half d_Kh[3*NELEM];
__device__ uint32_t d_Vt[3*8*32*TPAIRS];   // [si][h][dim][tokpair] packed half2
__device__ __half d_Nbuf[(size_t)NSLOTS*128*256];  // unnormalized PV per frame-pair
__device__ float d_Dbuf[(size_t)NSLOTS*128*8];     // exp-sums per frame-pair [slot][q][h]
__device__ __half d_G[NTOK*KG];            // combined attn [token][si*256+k] fp16
__device__ __half d_Wqkvh[9*HH*HH];        // QKV weights transposed [si*3+which][n][k] fp16
__device__ __half d_Wgt[HH*KG];            // gproj weights [n][si*256+k] fp16
__device__ float d_bsum[HH];               // 0.25*(bo0+bo1+bo2)
__device__ float d_vsum[2*F*HH];           // per-iter per-frame column sums of gproj acc
__device__ float d_sig[NTOK];              // iter-0 sigmoid values
__device__ float d_sigacc[NTOK];           // iter-1 raw halt dots (pre-sigmoid)

__device__ __forceinline__ uint32_t packh2(float a, float b) {
    __half2 h = __floats2half2_rn(a, b);
    return *(uint32_t*)&h;
}

__device__ __forceinline__ uint32_t h2ex2(uint32_t x) {
    uint32_t y;
    asm("ex2.approx.f16x2 %0, %1;" : "=r"(y) : "r"(x));
    return y;
}

__device__ __forceinline__ void cp16(uint32_t saddr, const void* g) {
    asm volatile("cp.async.cg.shared.global [%0], [%1], 16;\n" :: "r"(saddr), "l"(g));
}
#define CP_COMMIT() asm volatile("cp.async.commit_group;\n" ::: "memory")
#define CP_WAIT1()  asm volatile("cp.async.wait_group 1;\n" ::: "memory")
#define CP_WAIT0()  asm volatile("cp.async.wait_group 0;\n" ::: "memory")

// mma.sync m16n8k16 fp16 -> fp32 accumulate in-place
__device__ __forceinline__ void mma_f16(float c[4], const uint32_t a[4],
                                        uint32_t b0, uint32_t b1)
{
    asm volatile(
        "mma.sync.aligned.m16n8k16.row.col.f32.f16.f16.f32 "
        "{%0,%1,%2,%3}, {%4,%5,%6,%7}, {%8,%9}, {%0,%1,%2,%3};\n"
        : "+f"(c[0]), "+f"(c[1]), "+f"(c[2]), "+f"(c[3])
        : "r"(a[0]), "r"(a[1]), "r"(a[2]), "r"(a[3]), "r"(b0), "r"(b1));
}

// =================== iter-0 halting + X->fp16 (fused) ===================
__global__ void __launch_bounds__(256)
halt_sig_k(const float* __restrict__ x, const float* __restrict__ hW,
           const float* __restrict__ hb, float* __restrict__ sig,
           __half* __restrict__ Xh)
{
    int warp = threadIdx.x >> 5;
    int lane = threadIdx.x & 31;
    int pos = blockIdx.x * 8 + warp;
    const float* xp0 = x + (size_t)pos * HH + lane * 8;
    const float* xp1 = x + (size_t)(pos + TPAIRS) * HH + lane * 8;
    const float* wp = hW + lane * 8;
    float4 a0 = *(const float4*)xp0;
    float4 a1 = *(const float4*)(xp0 + 4);
    float4 b0 = *(const float4*)xp1;
    float4 b1 = *(const float4*)(xp1 + 4);
    float4 w0 = *(const float4*)wp;
    float4 w1 = *(const float4*)(wp + 4);
    uint4 ha, hb4;
    ha.x = packh2(a0.x, a0.y);  ha.y = packh2(a0.z, a0.w);
    ha.z = packh2(a1.x, a1.y);  ha.w = packh2(a1.z, a1.w);
    hb4.x = packh2(b0.x, b0.y); hb4.y = packh2(b0.z, b0.w);
    hb4.z = packh2(b1.x, b1.y); hb4.w = packh2(b1.z, b1.w);
    *(uint4*)&Xh[(size_t)pos * HH + lane * 8] = ha;
    *(uint4*)&Xh[(size_t)(pos + TPAIRS) * HH + lane * 8] = hb4;

    float acc0 = a0.x * w0.x + a0.y * w0.y + a0.z * w0.z + a0.w * w0.w
               + a1.x * w1.x + a1.y * w1.y + a1.z * w1.z + a1.w * w1.w;
    float acc1 = b0.x * w0.x + b0.y * w0.y + b0.z * w0.z + b0.w * w0.w
               + b1.x * w1.x + b1.y * w1.y + b1.z * w1.z + b1.w * w1.w;
    #pragma unroll
    for (int off = 16; off > 0; off >>= 1) {
        acc0 += __shfl_xor_sync(0xffffffffu, acc0, off);
        acc1 += __shfl_xor_sync(0xffffffffu, acc1, off);
    }
    if (lane == 0) {
        sig[pos] = 1.f / (1.f + __expf(-(acc0 + hb[0])));
        sig[pos + TPAIRS] = 1.f / (1.f + __expf(-(acc1 + hb[0])));
    }
}

// =================== merged setup: weight conversions + misc init ===================
__global__ void __launch_bounds__(256)
setup_k(const float* __restrict__ Wq, const float* __restrict__ Wk,
        const float* __restrict__ Wv, const float* __restrict__ Wo,
        const float* __restrict__ bo,
        __half* __restrict__ Wqkvh, __half* __restrict__ Wgt,
        float* __restrict__ bsum, float* __restrict__ vsum,
        float* __restrict__ sigacc)
{
    __shared__ float t[32][33];
    int z = blockIdx.z;
    int tx = threadIdx.x, ty = threadIdx.y;     // 32 x 8
    if (z == 12) {
        if (blockIdx.x != 0 || blockIdx.y != 0) return;
        int tid = ty * 32 + tx;
        if (tid < HH) bsum[tid] = 0.25f * (bo[tid] + bo[HH + tid] + bo[2 * HH + tid]);
        for (int i = tid; i < 2 * F * HH; i += 256) vsum[i] = 0.f;
        for (int i = tid; i < NTOK; i += 256) sigacc[i] = 0.f;
        return;
    }
    int k0 = blockIdx.x * 32, n0 = blockIdx.y * 32;
    if (z < 9) {
        int si = z / 3, which = z - si * 3;
        const float* W = (which == 0) ? Wq : ((which == 1) ? Wk : Wv);
        const float* src = W + (size_t)si * HH * HH;
        __half* dst = Wqkvh + (size_t)z * HH * HH;
        #pragma unroll
        for (int r = ty; r < 32; r += 8)
            t[r][tx] = src[(size_t)(k0 + r) * HH + n0 + tx];
        __syncthreads();
        #pragma unroll
        for (int r = ty; r < 32; r += 8)
            dst[(size_t)(n0 + r) * HH + k0 + tx] = __float2half(t[tx][r]);
    } else {
        int si = z - 9;
        const float* src = Wo + (size_t)si * HH * HH;
        #pragma unroll
        for (int r = ty; r < 32; r += 8)
            t[r][tx] = src[(size_t)(k0 + r) * HH + n0 + tx];
        __syncthreads();
        #pragma unroll
        for (int r = ty; r < 32; r += 8)
            Wgt[(size_t)(n0 + r) * KG + si * HH + k0 + tx] = __float2half(t[tx][r]);
    }
}

// =================== fp16 mma GEMM mainloop, tile 128x128, 2-stage pipeline ===================
#define OSTRIDE 36
#define GBUF (128 * OSTRIDE)
__device__ __forceinline__ void mma_mainloop(const __half* __restrict__ A, int bm, int lda,
                                             const __half* __restrict__ Bw, int bn, int ldb,
                                             int kdim, uint32_t* sbuf, float acc[2][8][4])
{
    const int tid  = threadIdx.x;
    const int warp = tid >> 5;
    const int lane = tid & 31;
    const int gid  = lane >> 2;
    const int tig  = lane & 3;
    const int wm = (warp & 3) * 32;
    const int wn = (warp >> 2) * 64;
    const uint32_t sb = (uint32_t)__cvta_generic_to_shared(sbuf);

    #pragma unroll
    for (int mt = 0; mt < 2; mt++)
        #pragma unroll
        for (int nt = 0; nt < 8; nt++)
            #pragma unroll
            for (int i = 0; i < 4; i++) acc[mt][nt][i] = 0.f;

    auto issue = [&](int kc, int st) {
        uint32_t aoff = sb + (uint32_t)(2 * st) * (GBUF * 4);
        uint32_t boff = aoff + GBUF * 4;
        for (int i = tid; i < 1024; i += 256) {
            int m = i >> 3, q = i & 7;
            uint32_t so = (uint32_t)(m * OSTRIDE + q * 4) * 4;
            cp16(aoff + so, &A[(size_t)(bm + m) * lda + kc + q * 8]);
            cp16(boff + so, &Bw[(size_t)(bn + m) * ldb + kc + q * 8]);
        }
        CP_COMMIT();
    };

    const int nchunks = kdim >> 6;
    issue(0, 0);
    for (int kci = 0; kci < nchunks; kci++) {
        const bool more = (kci + 1) < nchunks;
        if (more) issue((kci + 1) * 64, (kci + 1) & 1);
        if (more) CP_WAIT1(); else CP_WAIT0();
        __syncthreads();
        uint32_t* As = sbuf + 2 * (kci & 1) * GBUF;
        uint32_t* Bs = As + GBUF;
        #pragma unroll
        for (int ks = 0; ks < 4; ks++) {
            uint32_t a[2][4];
            #pragma unroll
            for (int mt = 0; mt < 2; mt++) {
                int r0 = (wm + mt * 16 + gid) * OSTRIDE + ks * 8;
                int r1 = (wm + mt * 16 + gid + 8) * OSTRIDE + ks * 8;
                a[mt][0] = As[r0 + tig];
                a[mt][1] = As[r1 + tig];
                a[mt][2] = As[r0 + tig + 4];
                a[mt][3] = As[r1 + tig + 4];
            }
            #pragma unroll
            for (int nt = 0; nt < 8; nt++) {
                int nr = (wn + nt * 8 + gid) * OSTRIDE + ks * 8;
                uint32_t b0 = Bs[nr + tig];
                uint32_t b1 = Bs[nr + tig + 4];
                #pragma unroll
                for (int mt = 0; mt < 2; mt++)
                    mma_f16(acc[mt][nt], a[mt], b0, b1);
            }
        }
        __syncthreads();
    }
}

// QKV mma GEMM: grid (18, 2, 9); z: si=z/3, which=z%3.
__global__ void __launch_bounds__(256)
gemm_qkv_mma_k(const __half* __restrict__ Xh, const __half* __restrict__ Wt,
               const float* __restrict__ bq, const float* __restrict__ bk,
               const float* __restrict__ bv,
               __half* __restrict__ Q, __half* __restrict__ K,
               uint32_t* __restrict__ Vt)
{
    __shared__ uint32_t sbuf[4 * GBUF];
    int z = blockIdx.z;
    int si = z / 3, which = z - si * 3;
    int bm = blockIdx.x * 128, bn = blockIdx.y * 128;

    float acc[2][8][4];
    mma_mainloop(Xh, bm, HH, Wt + (size_t)z * HH * HH, bn, HH, HH, sbuf, acc);

    const int tid  = threadIdx.x;
    const int warp = tid >> 5;
    const int lane = tid & 31;
    const int gid  = lane >> 2;
    const int tig  = lane & 3;
    const int wm = (warp & 3) * 32;
    const int wn = (warp >> 2) * 64;

    if (which < 2) {
        const float* bias = ((which == 0) ? bq : bk) + si * HH;
        __half* C = ((which == 0) ? Q : K) + (size_t)si * NELEM;
        float oscale = (which == 0) ? (0.17677669529663687f * 1.4426950408889634f) : 1.0f;
        #pragma unroll
        for (int nt = 0; nt < 8; nt++) {
            int n = bn + wn + nt * 8 + 2 * tig;
            float b0 = bias[n], b1 = bias[n + 1];
            #pragma unroll
            for (int mt = 0; mt < 2; mt++) {
                int m = bm + wm + mt * 16 + gid;
                *(uint32_t*)&C[(size_t)m * 256 + n] =
                    packh2((acc[mt][nt][0] + b0) * oscale, (acc[mt][nt][1] + b1) * oscale);
                *(uint32_t*)&C[(size_t)(m + 8) * 256 + n] =
                    packh2((acc[mt][nt][2] + b0) * oscale, (acc[mt][nt][3] + b1) * oscale);
            }
        }
    } else {
        const float* bias = bv + si * HH;
        __half* stag = (__half*)sbuf;            // [128 tok][stride 130]
        __syncthreads();
        #pragma unroll
        for (int nt = 0; nt < 8; nt++) {
            int nl = wn + nt * 8 + 2 * tig;
            float b0 = bias[bn + nl], b1 = bias[bn + nl + 1];
            #pragma unroll
            for (int mt = 0; mt < 2; mt++) {
                int ml = wm + mt * 16 + gid;
                *(uint32_t*)&stag[ml * 130 + nl] =
                    packh2(acc[mt][nt][0] + b0, acc[mt][nt][1] + b1);
                *(uint32_t*)&stag[(ml + 8) * 130 + nl] =
                    packh2(acc[mt][nt][2] + b0, acc[mt][nt][3] + b1);
            }
        }
        __syncthreads();
        const int tpg0 = bm >> 1;
        uint32_t* vtb = Vt + (size_t)si * 8 * 32 * TPAIRS;
        #pragma unroll
        for (int j = tid; j < 8192; j += 256) {
            int tp = j & 63;
            int nl = j >> 6;
            int ncol = bn + nl;
            int h = ncol >> 5, d = ncol & 31;
            __half lo = stag[(2 * tp) * 130 + nl];
            __half hi = stag[(2 * tp + 1) * 130 + nl];
            __half2 pr = __halves2half2(lo, hi);
            vtb[((size_t)(h * 32 + d)) * TPAIRS + tpg0 + tp] = *(uint32_t*)&pr;
        }
    }
}

// =================== frame-pair attention: N/D, single-shot K/V load ===================
#define KPSTRIDE 36
#define VTSTRIDE2 68    // 64 keypairs + pad; bank = 4*gid+tig -> conflict-free
__global__ void __launch_bounds__(256, 3)
attn_nd_k(const __half* __restrict__ Qg, const __half* __restrict__ Kg,
          const uint32_t* __restrict__ Vt, __half* __restrict__ Nbuf,
          float* __restrict__ Dbuf)
{
    __shared__ uint32_t Kp[128 * KPSTRIDE];   // [key][kpair]
    __shared__ uint32_t Vs[32 * VTSTRIDE2];   // [dim][keypair]

    int pid = blockIdx.x;
    int si, fq, d, slot, s;
    if (pid < 198)      { si = 2; s = 6; fq = pid / 11; d = pid - fq * 11; slot = SBASE2 + fq * 11 + d; }
    else if (pid < 324) { pid -= 198; si = 1; s = 4; fq = pid / 7; d = pid - fq * 7; slot = SBASE1 + fq * 7 + d; }
    else                { pid -= 324; si = 0; s = 2; fq = pid / 3; d = pid - fq * 3; slot = SBASE0 + fq * 3 + d; }
    const int fk = fq + d - (s - 1);
    if (fk < 0 || fk > 17) return;

    const int tid  = threadIdx.x;
    const int warp = tid >> 5;
    const int lane = tid & 31;
    const int gid  = lane >> 2;
    const int tig  = lane & 3;
    const int h    = blockIdx.y;

    const __half* Q = Qg + (size_t)si * NELEM;
    const __half* K = Kg + (size_t)si * NELEM;
    const uint32_t* Vtb = Vt + ((size_t)si * 8 + h) * 32 * TPAIRS;

    const uint32_t kpb = (uint32_t)__cvta_generic_to_shared(Kp);
    const uint32_t vsb = (uint32_t)__cvta_generic_to_shared(Vs);

    // single-shot load: all 128 keys of K + all 64 keypairs of V
    {
        const __half* kg = K + ((size_t)(fk * PP)) * HH + h * 32;
        const uint32_t* vg = Vtb + ((fk * PP) >> 1);
        #pragma unroll
        for (int j = 0; j < 2; j++) {
            int i = tid + j * 256;             // [0,512)
            int key = i >> 2, q = i & 3;
            cp16(kpb + (uint32_t)(key * KPSTRIDE + q * 4) * 4,
                 kg + (size_t)key * HH + q * 8);
        }
        #pragma unroll
        for (int j = 0; j < 2; j++) {
            int i = tid + j * 256;             // [0,512)
            int dd = i >> 4, q = i & 15;
            cp16(vsb + (uint32_t)(dd * VTSTRIDE2 + q * 4) * 4,
                 vg + (size_t)dd * TPAIRS + q * 4);
        }
        CP_COMMIT();
    }

    const int qloc = warp * 16 + gid;
    const int qrow = fq * PP + qloc;
    uint32_t qa[2][4];
    #pragma unroll
    for (int ks = 0; ks < 2; ks++) {
        const uint32_t* q0 = (const uint32_t*)(Q + (size_t)qrow * HH + h * 32 + ks * 16);
        const uint32_t* q1 = (const uint32_t*)(Q + (size_t)(qrow + 8) * HH + h * 32 + ks * 16);
        qa[ks][0] = q0[tig];
        qa[ks][1] = q1[tig];
        qa[ks][2] = q0[tig + 4];
        qa[ks][3] = q1[tig + 4];
    }

    float o[4][4];
    #pragma unroll
    for (int v = 0; v < 4; v++)
        #pragma unroll
        for (int i = 0; i < 4; i++) o[v][i] = 0.f;
    float l0 = 0.f, l1 = 0.f;

    CP_WAIT0();
    __syncthreads();

    #pragma unroll
    for (int kt = 0; kt < 2; kt++) {
        float sc[8][4];
        #pragma unroll
        for (int t = 0; t < 8; t++) {
            sc[t][0] = sc[t][1] = sc[t][2] = sc[t][3] = 0.f;
            const int krow = (64 * kt + 8 * t + gid) * KPSTRIDE;
            #pragma unroll
            for (int ks = 0; ks < 2; ks++) {
                uint32_t b0 = Kp[krow + ks * 8 + tig];
                uint32_t b1 = Kp[krow + ks * 8 + tig + 4];
                mma_f16(sc[t], qa[ks], b0, b1);
            }
        }

        uint32_t e0[8], e1[8];
        #pragma unroll
        for (int t = 0; t < 8; t++) {
            e0[t] = h2ex2(packh2(sc[t][0], sc[t][1]));
            e1[t] = h2ex2(packh2(sc[t][2], sc[t][3]));
            float2 f0 = __half22float2(*(__half2*)&e0[t]);
            float2 f1 = __half22float2(*(__half2*)&e1[t]);
            l0 += f0.x + f0.y;
            l1 += f1.x + f1.y;
        }

        #pragma unroll
        for (int u = 0; u < 4; u++) {
            uint32_t pa[4];
            pa[0] = e0[2*u];
            pa[1] = e1[2*u];
            pa[2] = e0[2*u+1];
            pa[3] = e1[2*u+1];
            #pragma unroll
            for (int v = 0; v < 4; v++) {
                uint32_t b0 = Vs[(gid + 8 * v) * VTSTRIDE2 + 32 * kt + 8 * u + tig];
                uint32_t b1 = Vs[(gid + 8 * v) * VTSTRIDE2 + 32 * kt + 8 * u + tig + 4];
                mma_f16(o[v], pa, b0, b1);
            }
        }
    }

    l0 += __shfl_xor_sync(0xffffffffu, l0, 1);
    l0 += __shfl_xor_sync(0xffffffffu, l0, 2);
    l1 += __shfl_xor_sync(0xffffffffu, l1, 1);
    l1 += __shfl_xor_sync(0xffffffffu, l1, 2);

    __half* Nb = Nbuf + ((size_t)slot * 128) * 256 + h * 32;
    #pragma unroll
    for (int v = 0; v < 4; v++) {
        *(uint32_t*)&Nb[(size_t)qloc * 256 + v * 8 + 2 * tig] = packh2(o[v][0], o[v][1]);
        *(uint32_t*)&Nb[(size_t)(qloc + 8) * 256 + v * 8 + 2 * tig] = packh2(o[v][2], o[v][3]);
    }
    if (tig == 0) {
        Dbuf[((size_t)slot * 128 + qloc) * 8 + h] = l0;
        Dbuf[((size_t)slot * 128 + qloc + 8) * 8 + h] = l1;
    }
}

// =================== combine: sliding-window N/D -> G ===================
__global__ void __launch_bounds__(256)
combine_k(const __half* __restrict__ Nbuf, const float* __restrict__ Dbuf,
          __half* __restrict__ G)
{
    const int t = blockIdx.x;
    const int c = threadIdx.x;
    const int f = t >> 7, pos = t & 127;
    const int hh = c >> 5;

    const int ss[3]    = {2, 4, 6};
    const int strd[3]  = {3, 7, 11};
    const int sbase[3] = {SBASE0, SBASE1, SBASE2};

    #pragma unroll
    for (int si = 0; si < 3; si++) {
        const int s = ss[si];
        const int slotbase = sbase[si] + f * strd[si];
        const int nw = F - s + 1;
        const int wlo = max(0, f - s + 1);
        const int whi = min(f, nw - 1);
        const int count = whi - wlo + 1;

        float num = 0.f, den = 0.f;
        const int d0 = wlo - f + s - 1;
        for (int dd = 0; dd < s; dd++) {
            int sl = slotbase + d0 + dd;
            num += __half2float(Nbuf[((size_t)sl * 128 + pos) * 256 + c]);
            den += Dbuf[((size_t)sl * 128 + pos) * 8 + hh];
        }
        float total = num / den;
        for (int w = wlo + 1; w <= whi; w++) {
            int slout = slotbase + (w - 1) - f + s - 1;
            int slin  = slotbase + w - f + 2 * s - 2;
            num += __half2float(Nbuf[((size_t)slin * 128 + pos) * 256 + c])
                 - __half2float(Nbuf[((size_t)slout * 128 + pos) * 256 + c]);
            den += Dbuf[((size_t)slin * 128 + pos) * 8 + hh]
                 - Dbuf[((size_t)slout * 128 + pos) * 8 + hh];
            total += num / den;
        }
        G[(size_t)t * KG + si * HH + c] = __float2half(total * (0.25f / (float)count));
    }
}

// =================== gproj GEMM + colsum + X + fused next-iter halt dot ===================
__global__ void __launch_bounds__(256)
gemm_gproj_mma_k(const __half* __restrict__ G, const __half* __restrict__ Wgt,
                 const float* __restrict__ bsum, float* __restrict__ vsum,
                 __half* __restrict__ Xh, const float* __restrict__ hW,
                 float* __restrict__ sigacc, int writeX)
{
    __shared__ uint32_t sbuf[4 * GBUF];
    int bm = blockIdx.x * 128, bn = blockIdx.y * 128;

    float acc[2][8][4];
    mma_mainloop(G, bm, KG, Wgt, bn, KG, KG, sbuf, acc);

    const int tid  = threadIdx.x;
    const int warp = tid >> 5;
    const int lane = tid & 31;
    const int gid  = lane >> 2;
    const int tig  = lane & 3;
    const int wm = (warp & 3) * 32;
    const int wn = (warp >> 2) * 64;
    const int f = bm >> 7;
    float* vs = vsum + f * HH;

    float hd[4] = {0.f, 0.f, 0.f, 0.f};

    #pragma unroll
    for (int nt = 0; nt < 8; nt++) {
        int n = bn + wn + nt * 8 + 2 * tig;
        float b0 = bsum[n], b1 = bsum[n + 1];
        float s0 = acc[0][nt][0] + acc[0][nt][2] + acc[1][nt][0] + acc[1][nt][2];
        float s1 = acc[0][nt][1] + acc[0][nt][3] + acc[1][nt][1] + acc[1][nt][3];
        #pragma unroll
        for (int off = 4; off < 32; off <<= 1) {
            s0 += __shfl_xor_sync(0xffffffffu, s0, off);
            s1 += __shfl_xor_sync(0xffffffffu, s1, off);
        }
        if (gid == 0) {
            atomicAdd(&vs[n], s0);
            atomicAdd(&vs[n + 1], s1);
        }
        if (writeX) {
            float hw0 = hW[n], hw1 = hW[n + 1];
            #pragma unroll
            for (int mt = 0; mt < 2; mt++) {
                int m = bm + wm + mt * 16 + gid;
                float v0 = acc[mt][nt][0] + b0, v1 = acc[mt][nt][1] + b1;
                float v2 = acc[mt][nt][2] + b0, v3 = acc[mt][nt][3] + b1;
                *(uint32_t*)&Xh[(size_t)m * 256 + n] = packh2(v0, v1);
                *(uint32_t*)&Xh[(size_t)(m + 8) * 256 + n] = packh2(v2, v3);
                hd[mt * 2]     += v0 * hw0 + v1 * hw1;
                hd[mt * 2 + 1] += v2 * hw0 + v3 * hw1;
            }
        }
    }

    if (writeX) {
        #pragma unroll
        for (int i = 0; i < 4; i++) {
            hd[i] += __shfl_xor_sync(0xffffffffu, hd[i], 1);
            hd[i] += __shfl_xor_sync(0xffffffffu, hd[i], 2);
        }
        if (tig == 0) {
            #pragma unroll
            for (int mt = 0; mt < 2; mt++) {
                int m = bm + wm + mt * 16 + gid;
                atomicAdd(&sigacc[m], hd[mt * 2]);
                atomicAdd(&sigacc[m + 8], hd[mt * 2 + 1]);
            }
        }
    }
}

// =================== classifier: ACT + weighted colsum combine + GEMV ===================
__global__ void classify_k(const float* __restrict__ vsum, const float* __restrict__ sig0,
                           const float* __restrict__ sigacc, const float* __restrict__ hb,
                           const float* __restrict__ bsum,
                           const float* __restrict__ clsW, const float* __restrict__ clsb,
                           float* __restrict__ out)
{
    __shared__ float cs[HH];
    __shared__ float pf0s[F], pf1s[F], w0s[F], w1s[F];
    int tid = threadIdx.x;        // 128
    int warp = tid >> 5, lane = tid & 31;

    if (warp == 0) {
        for (int f = 0; f < F; f++) {
            float4 v = *(const float4*)&sig0[f * PP + lane * 4];
            float a = v.x + v.y + v.z + v.w;
            #pragma unroll
            for (int off = 16; off > 0; off >>= 1)
                a += __shfl_xor_sync(0xffffffffu, a, off);
            if (lane == 0) pf0s[f] = a * (1.f / 128.f);
        }
    } else if (warp == 1) {
        float hbv = hb[0];
        for (int f = 0; f < F; f++) {
            float4 v = *(const float4*)&sigacc[f * PP + lane * 4];
            float a = 1.f / (1.f + __expf(-(v.x + hbv)))
                    + 1.f / (1.f + __expf(-(v.y + hbv)))
                    + 1.f / (1.f + __expf(-(v.z + hbv)))
                    + 1.f / (1.f + __expf(-(v.w + hbv)));
            #pragma unroll
            for (int off = 16; off > 0; off >>= 1)
                a += __shfl_xor_sync(0xffffffffu, a, off);
            if (lane == 0) pf1s[f] = a * (1.f / 128.f);
        }
    }
    __syncthreads();
    if (tid == 0) {
        for (int f = 0; f < F; f++) {
            float pf0 = pf0s[f], pf1 = pf1s[f];
            float nh   = (pf0 > 0.99f) ? 1.f : 0.f;
            float run2 = (pf0 <= 0.99f) ? 1.f : 0.f;
            float pt = pf0 * run2;
            float rt = nh * (1.f - pt);
            pt = pt + nh * rt;
            w0s[f] = pf0 * run2 + nh * rt;
            float run = (pt < 1.0f) ? 1.f : 0.f;
            float t = pt + pf1 * run;
            nh   = (t > 0.99f)  ? run : 0.f;
            run2 = (t <= 0.99f) ? run : 0.f;
            pt = pt + pf1 * run2;
            rt = rt + nh * (1.f - pt);
            pt = pt + nh * rt;
            w1s[f] = pf1 * run2 + nh * rt;
        }
    }
    __syncthreads();

    for (int h = tid; h < HH; h += 128) {
        float s = 0.f;
        float bb = 128.f * bsum[h];
        #pragma unroll
        for (int f = 0; f < F; f++) {
            float w0 = w0s[f], w1 = w1s[f];
            float v0 = vsum[f * HH + h] + bb;
            float v1 = vsum[F * HH + f * HH + h] + bb;
            s += w1 * v1 + (1.f - w1) * w0 * v0;
        }
        cs[h] = s;
    }
    __syncthreads();
    int j = blockIdx.x * 128 + tid;
    if (j < NCLS) {
        float acc = clsb[j];
        for (int h = 0; h < HH; h++) acc = fmaf(cs[h], clsW[h * NCLS + j], acc);
        out[j] = acc;
    }
}

// =================== host launch ===================
extern "C" void kernel_launch(void* const* d_in, const int* in_sizes, int n_in,
                              void* d_out, int out_size)
{
    (void)in_sizes; (void)n_in; (void)out_size;
    const float* embed  = (const float*)d_in[0];
    const float* halt_W = (const float*)d_in[3];
    const float* halt_b = (const float*)d_in[4];
    const float* cls_W  = (const float*)d_in[8];
    const float* cls_b  = (const float*)d_in[9];
    const float* Wq = (const float*)d_in[10];
    const float* bq = (const float*)d_in[11];
    const float* Wk = (const float*)d_in[12];
    const float* bk = (const float*)d_in[13];
    const float* Wv = (const float*)d_in[14];
    const float* bv = (const float*)d_in[15];
    const float* Wo = (const float*)d_in[16];
    const float* bo = (const float*)d_in[17];
    float* out = (float*)d_out;

    float *sig, *sigacc, *bsum, *vsum, *Dbuf;
    __half *Xh, *Qh, *Kh, *Nbuf, *G, *Wqkvh, *Wgt;
    uint32_t *Vt;
    cudaGetSymbolAddress((void**)&Xh,      d_Xh);
    cudaGetSymbolAddress((void**)&Qh,      d_Qh);
    cudaGetSymbolAddress((void**)&Kh,      d_Kh);
    cudaGetSymbolAddress((void**)&Vt,      d_Vt);
    cudaGetSymbolAddress((void**)&Nbuf,    d_Nbuf);
    cudaGetSymbolAddress((void**)&Dbuf,    d_Dbuf);
    cudaGetSymbolAddress((void**)&G,       d_G);
    cudaGetSymbolAddress((void**)&Wqkvh,   d_Wqkvh);
    cudaGetSymbolAddress((void**)&Wgt,     d_Wgt);
    cudaGetSymbolAddress((void**)&bsum,    d_bsum);
    cudaGetSymbolAddress((void**)&vsum,    d_vsum);
    cudaGetSymbolAddress((void**)&sig,     d_sig);
    cudaGetSymbolAddress((void**)&sigacc,  d_sigacc);

    // merged setup: weights + bias-sum + zeroing
    {
        dim3 b(32, 8);
        dim3 g(8, 8, 13);
        setup_k<<<g, b>>>(Wq, Wk, Wv, Wo, bo, Wqkvh, Wgt, bsum, vsum, sigacc);
    }
    // iter-0 halting + fp16 X conversion (fused)
    halt_sig_k<<<TPAIRS / 8, 256>>>(embed, halt_W, halt_b, sig, Xh);

    for (int iter = 0; iter < 2; iter++) {
        // QKV (fp16 tensor GEMM) for all 3 scales; V written transposed (Vt)
        dim3 gq(NTOK / 128, 2, 9);
        gemm_qkv_mma_k<<<gq, 256>>>(Xh, Wqkvh, bq, bk, bv, Qh, Kh, Vt);

        // frame-pair attention (N/D decomposition): 378 slots x 8 heads
        dim3 ga(NSLOTS, 8);
        attn_nd_k<<<ga, 256>>>(Qh, Kh, Vt, Nbuf, Dbuf);

        // sliding-window combine -> G
        combine_k<<<NTOK, 256>>>(Nbuf, Dbuf, G);

        // fused projection GEMM + colsum (+Xh + next-iter halt dot on iter 0)
        dim3 gg(NTOK / 128, 2);
        gemm_gproj_mma_k<<<gg, 256>>>(G, Wgt, bsum, vsum + iter * F * HH, Xh,
                                      halt_W, sigacc, iter == 0 ? 1 : 0);
    }
    classify_k<<<(NCLS + 127) / 128, 128>>>(vsum, sig, sigacc, halt_b, bsum,
                                            cls_W, cls_b, out);
}